// round 14
// baseline (speedup 1.0000x reference)
#include <cuda_runtime.h>
#include <cuda_fp16.h>

// CompositeValueNoise v7:
//   Launch 1: single-pass bucket append (atomicAdd per coarse 16^3 cell into a
//             padded per-cell array). No histogram, no scan, no barriers.
//   Launch 2: bucket-tiled noise kernel (1 CTA per coarse cell; V16 f32,
//             V32/V64/V128 fp16 z-pair slots; f32x2 lerp tree). Each CTA
//             zeroes its own counter after reading it -> replay-safe.

#define MAX_POINTS 2000000
#define NGC 4096             // 16^3 coarse cells
#define CAPC 704             // per-cell capacity (mean 488, +9.8 sigma)
#define GROUP_THREADS 256

__device__ int    g_cnt[NGC];            // static zero-init; noise kernel re-zeros
__device__ float4 g_pts[NGC * CAPC];     // 46 MB padded bucket storage

// ---------------------------------------------------------------------------
// append kernel: one pass, one atomic per point
// ---------------------------------------------------------------------------
__global__ void __launch_bounds__(256)
append_kernel(const float* __restrict__ x, int n) {
    int i = blockIdx.x * blockDim.x + threadIdx.x;
    if (i >= n) return;
    float px = __ldg(x + 3 * i);
    float py = __ldg(x + 3 * i + 1);
    float pz = __ldg(x + 3 * i + 2);
    int kx = min((int)(px * 16.0f), 15);
    int ky = min((int)(py * 16.0f), 15);
    int kz = min((int)(pz * 16.0f), 15);
    int g = (kx * 16 + ky) * 16 + kz;
    int r = atomicAdd(&g_cnt[g], 1);
    if (r < CAPC) g_pts[g * CAPC + r] = make_float4(px, py, pz, __int_as_float(i));
}

// ---------------------------------------------------------------------------
// packed f32x2 helpers
// ---------------------------------------------------------------------------
struct f2 { unsigned long long v; };

__device__ __forceinline__ f2 f2pk(float lo, float hi) {
    f2 r; asm("mov.b64 %0,{%1,%2};" : "=l"(r.v) : "f"(lo), "f"(hi)); return r;
}
__device__ __forceinline__ void f2up(f2 a, float& lo, float& hi) {
    asm("mov.b64 {%0,%1},%2;" : "=f"(lo), "=f"(hi) : "l"(a.v));
}
__device__ __forceinline__ f2 f2fma(f2 a, f2 b, f2 c) {
    f2 r; asm("fma.rn.f32x2 %0,%1,%2,%3;" : "=l"(r.v) : "l"(a.v), "l"(b.v), "l"(c.v));
    return r;
}
__device__ __forceinline__ f2 f2neg(f2 a) {
    f2 r; r.v = a.v ^ 0x8000000080000000ULL; return r;
}
__device__ __forceinline__ f2 f2lerp(f2 a, f2 b, f2 w, f2 nw) {
    return f2fma(w, b, f2fma(nw, a, a));
}
struct f2x2 { f2 a, b; };

__device__ __forceinline__ f2 h2f2(__half2 h) {
    float2 f = __half22float2(h);
    return f2pk(f.x, f.y);
}

__device__ __forceinline__ float smoothw(float t) {
    return (3.0f - 2.0f * t) * t * t;
}

// ---------------------------------------------------------------------------
// f32 level from smem float4 tile
// ---------------------------------------------------------------------------
template <int RES, int SX, int SY>
__device__ __forceinline__ f2x2 noise_f32(const float4* __restrict__ sm,
                                          int bx, int by, int bz,
                                          float px, float py, float pz) {
    const float r = (float)RES;
    float sx = px * r, sy = py * r, sz = pz * r;
    float fx = floorf(sx), fy = floorf(sy), fz = floorf(sz);
    float tx = sx - fx, ty = sy - fy, tz = sz - fz;
    int lx = (int)fx - bx, ly = (int)fy - by, lz = (int)fz - bz;

    f2 wz = f2pk(smoothw(tz), smoothw(tz)); f2 nwz = f2neg(wz);
    f2 wy = f2pk(smoothw(ty), smoothw(ty)); f2 nwy = f2neg(wy);
    f2 wx = f2pk(smoothw(tx), smoothw(tx)); f2 nwx = f2neg(wx);

    int idx = lx * SX + ly * SY + lz;
    float4 c000 = sm[idx],           c001 = sm[idx + 1];
    float4 c010 = sm[idx + SY],      c011 = sm[idx + SY + 1];
    float4 c100 = sm[idx + SX],      c101 = sm[idx + SX + 1];
    float4 c110 = sm[idx + SX + SY], c111 = sm[idx + SX + SY + 1];

    f2 z00a = f2lerp(f2pk(c000.x, c000.y), f2pk(c001.x, c001.y), wz, nwz);
    f2 z00b = f2lerp(f2pk(c000.z, c000.w), f2pk(c001.z, c001.w), wz, nwz);
    f2 z01a = f2lerp(f2pk(c010.x, c010.y), f2pk(c011.x, c011.y), wz, nwz);
    f2 z01b = f2lerp(f2pk(c010.z, c010.w), f2pk(c011.z, c011.w), wz, nwz);
    f2 z10a = f2lerp(f2pk(c100.x, c100.y), f2pk(c101.x, c101.y), wz, nwz);
    f2 z10b = f2lerp(f2pk(c100.z, c100.w), f2pk(c101.z, c101.w), wz, nwz);
    f2 z11a = f2lerp(f2pk(c110.x, c110.y), f2pk(c111.x, c111.y), wz, nwz);
    f2 z11b = f2lerp(f2pk(c110.z, c110.w), f2pk(c111.z, c111.w), wz, nwz);

    f2 y0a = f2lerp(z00a, z01a, wy, nwy);
    f2 y0b = f2lerp(z00b, z01b, wy, nwy);
    f2 y1a = f2lerp(z10a, z11a, wy, nwy);
    f2 y1b = f2lerp(z10b, z11b, wy, nwy);

    f2x2 o;
    o.a = f2lerp(y0a, y1a, wx, nwx);
    o.b = f2lerp(y0b, y1b, wx, nwx);
    return o;
}

// ---------------------------------------------------------------------------
// fp16 level from smem z-pair tile
// ---------------------------------------------------------------------------
template <int RES, int SX, int SY>
__device__ __forceinline__ f2x2 noise_f16(const uint4* __restrict__ smp,
                                          int bx, int by, int bz,
                                          float px, float py, float pz) {
    const float r = (float)RES;
    float sx = px * r, sy = py * r, sz = pz * r;
    float fx = floorf(sx), fy = floorf(sy), fz = floorf(sz);
    float tx = sx - fx, ty = sy - fy, tz = sz - fz;
    int lx = (int)fx - bx, ly = (int)fy - by, lz = (int)fz - bz;

    __half2 wz2 = __float2half2_rn(smoothw(tz));
    f2 wy = f2pk(smoothw(ty), smoothw(ty)); f2 nwy = f2neg(wy);
    f2 wx = f2pk(smoothw(tx), smoothw(tx)); f2 nwx = f2neg(wx);

    int idx = lx * SX + ly * SY + lz;
    uint4 q00 = smp[idx];
    uint4 q01 = smp[idx + SY];
    uint4 q10 = smp[idx + SX];
    uint4 q11 = smp[idx + SX + SY];

    #define ZL(q, out_a, out_b)                                                    \
        {                                                                          \
            __half2 a0 = *reinterpret_cast<const __half2*>(&(q).x);                \
            __half2 b0 = *reinterpret_cast<const __half2*>(&(q).y);                \
            __half2 a1 = *reinterpret_cast<const __half2*>(&(q).z);                \
            __half2 b1 = *reinterpret_cast<const __half2*>(&(q).w);                \
            out_a = __hfma2(wz2, __hsub2(a1, a0), a0);                             \
            out_b = __hfma2(wz2, __hsub2(b1, b0), b0);                             \
        }
    __half2 r00a, r00b, r01a, r01b, r10a, r10b, r11a, r11b;
    ZL(q00, r00a, r00b);
    ZL(q01, r01a, r01b);
    ZL(q10, r10a, r10b);
    ZL(q11, r11a, r11b);
    #undef ZL

    f2 y0a = f2lerp(h2f2(r00a), h2f2(r01a), wy, nwy);
    f2 y0b = f2lerp(h2f2(r00b), h2f2(r01b), wy, nwy);
    f2 y1a = f2lerp(h2f2(r10a), h2f2(r11a), wy, nwy);
    f2 y1b = f2lerp(h2f2(r10b), h2f2(r11b), wy, nwy);

    f2x2 o;
    o.a = f2lerp(y0a, y1a, wx, nwx);
    o.b = f2lerp(y0b, y1b, wx, nwx);
    return o;
}

// ---------------------------------------------------------------------------
// grouped noise kernel: one CTA per coarse cell, reads its padded bucket
// ---------------------------------------------------------------------------
__global__ void __launch_bounds__(GROUP_THREADS)
noise_group_kernel(const float4* __restrict__ V16,
                   const float4* __restrict__ V32,
                   const float4* __restrict__ V64,
                   const float4* __restrict__ V128,
                   float4* __restrict__ out) {
    int g = blockIdx.x;
    __shared__ int s_cnt;
    if (threadIdx.x == 0) {
        int c = g_cnt[g];
        s_cnt = min(c, CAPC);
        g_cnt[g] = 0;                    // reset for next graph replay
    }
    __syncthreads();
    int cnt = s_cnt;
    if (cnt == 0) return;

    int cx = g >> 8, cy = (g >> 4) & 15, cz = g & 15;

    __shared__ uint4  smP128[648];
    __shared__ uint4  smP64[100];
    __shared__ uint4  smP32[18];
    __shared__ float4 smV16[8];

    int tid = threadIdx.x;

    #define PACK_PAIR(c0, c1, q)                                 \
        {                                                        \
            __half2 h0a = __floats2half2_rn((c0).x, (c0).y);     \
            __half2 h0b = __floats2half2_rn((c0).z, (c0).w);     \
            __half2 h1a = __floats2half2_rn((c1).x, (c1).y);     \
            __half2 h1b = __floats2half2_rn((c1).z, (c1).w);     \
            (q).x = *reinterpret_cast<unsigned*>(&h0a);          \
            (q).y = *reinterpret_cast<unsigned*>(&h0b);          \
            (q).z = *reinterpret_cast<unsigned*>(&h1a);          \
            (q).w = *reinterpret_cast<unsigned*>(&h1b);          \
        }

    for (int t = tid; t < 648; t += GROUP_THREADS) {
        int lx = t / 72, ly = (t / 8) % 9, lz = t % 8;
        long ofs = ((long)(8 * cx + lx) * 129 + (8 * cy + ly)) * 129 + (8 * cz + lz);
        float4 c0 = __ldg(V128 + ofs);
        float4 c1 = __ldg(V128 + ofs + 1);
        uint4 q; PACK_PAIR(c0, c1, q);
        smP128[t] = q;
    }
    for (int t = tid; t < 126; t += GROUP_THREADS) {
        if (t < 100) {
            int lx = t / 20, ly = (t / 4) % 5, lz = t % 4;
            long ofs = ((long)(4 * cx + lx) * 65 + (4 * cy + ly)) * 65 + (4 * cz + lz);
            float4 c0 = __ldg(V64 + ofs);
            float4 c1 = __ldg(V64 + ofs + 1);
            uint4 q; PACK_PAIR(c0, c1, q);
            smP64[t] = q;
        } else if (t < 118) {
            int u = t - 100;
            int lx = u / 6, ly = (u / 2) % 3, lz = u % 2;
            long ofs = ((long)(2 * cx + lx) * 33 + (2 * cy + ly)) * 33 + (2 * cz + lz);
            float4 c0 = __ldg(V32 + ofs);
            float4 c1 = __ldg(V32 + ofs + 1);
            uint4 q; PACK_PAIR(c0, c1, q);
            smP32[u] = q;
        } else {
            int u = t - 118;
            int lx = (u >> 2) & 1, ly = (u >> 1) & 1, lz = u & 1;
            smV16[lx * 4 + ly * 2 + lz] =
                __ldg(V16 + ((cx + lx) * 17 + (cy + ly)) * 17 + (cz + lz));
        }
    }
    #undef PACK_PAIR
    __syncthreads();

    const float4* __restrict__ bucket = g_pts + (long)g * CAPC;
    for (int j = tid; j < cnt; j += GROUP_THREADS) {
        float4 p = bucket[j];
        float px = p.x, py = p.y, pz = p.z;
        int orig = __float_as_int(p.w);

        f2x2 acc = noise_f32<16, 4, 2>(smV16, cx, cy, cz, px, py, pz);

        f2x2 t32 = noise_f16<32, 6, 2>(smP32, 2 * cx, 2 * cy, 2 * cz, px, py, pz);
        f2 m05 = f2pk(0.5f, 0.5f);
        acc.a = f2fma(m05, t32.a, acc.a);
        acc.b = f2fma(m05, t32.b, acc.b);

        f2x2 t64 = noise_f16<64, 20, 4>(smP64, 4 * cx, 4 * cy, 4 * cz, px, py, pz);
        f2 m025 = f2pk(0.25f, 0.25f);
        acc.a = f2fma(m025, t64.a, acc.a);
        acc.b = f2fma(m025, t64.b, acc.b);

        f2x2 t128 = noise_f16<128, 72, 8>(smP128, 8 * cx, 8 * cy, 8 * cz, px, py, pz);
        f2 m0125 = f2pk(0.125f, 0.125f);
        acc.a = f2fma(m0125, t128.a, acc.a);
        acc.b = f2fma(m0125, t128.b, acc.b);

        float4 o;
        f2up(acc.a, o.x, o.y);
        f2up(acc.b, o.z, o.w);
        out[orig] = o;
    }
}

// ---------------------------------------------------------------------------
// fallback (unsorted, full f32) if n exceeds bucket capacity assumptions
// ---------------------------------------------------------------------------
__device__ __forceinline__ float4 lerp4g(const float4 a, const float4 b, const float t) {
    return make_float4(fmaf(t, b.x - a.x, a.x),
                       fmaf(t, b.y - a.y, a.y),
                       fmaf(t, b.z - a.z, a.z),
                       fmaf(t, b.w - a.w, a.w));
}
template <int RES>
__device__ __forceinline__ float4 noise_level(const float4* __restrict__ V,
                                              float px, float py, float pz) {
    const float r = (float)RES;
    float sx = px * r, sy = py * r, sz = pz * r;
    float fx = floorf(sx), fy = floorf(sy), fz = floorf(sz);
    float tx = sx - fx, ty = sy - fy, tz = sz - fz;
    int ix = min((int)fx, RES - 1);
    int iy = min((int)fy, RES - 1);
    int iz = min((int)fz, RES - 1);
    float wx = smoothw(tx), wy = smoothw(ty), wz = smoothw(tz);
    const int S = RES + 1, SY = S, SX = S * S;
    int base = (ix * S + iy) * S + iz;
    float4 c000 = __ldg(V + base);
    float4 c001 = __ldg(V + base + 1);
    float4 c010 = __ldg(V + base + SY);
    float4 c011 = __ldg(V + base + SY + 1);
    float4 c100 = __ldg(V + base + SX);
    float4 c101 = __ldg(V + base + SX + 1);
    float4 c110 = __ldg(V + base + SX + SY);
    float4 c111 = __ldg(V + base + SX + SY + 1);
    float4 az = lerp4g(c000, c001, wz);
    float4 bz = lerp4g(c010, c011, wz);
    float4 cz = lerp4g(c100, c101, wz);
    float4 dz = lerp4g(c110, c111, wz);
    float4 ay = lerp4g(az, bz, wy);
    float4 by = lerp4g(cz, dz, wy);
    return lerp4g(ay, by, wx);
}

__global__ void __launch_bounds__(256)
noise_direct_kernel(const float* __restrict__ x,
                    const float4* __restrict__ V16,
                    const float4* __restrict__ V32,
                    const float4* __restrict__ V64,
                    const float4* __restrict__ V128,
                    float4* __restrict__ out,
                    int n) {
    int i = blockIdx.x * blockDim.x + threadIdx.x;
    if (i >= n) return;
    float px = x[3 * i], py = x[3 * i + 1], pz = x[3 * i + 2];
    float4 acc = noise_level<16>(V16, px, py, pz);
    float4 t;
    t = noise_level<32>(V32, px, py, pz);
    acc.x = fmaf(0.5f, t.x, acc.x); acc.y = fmaf(0.5f, t.y, acc.y);
    acc.z = fmaf(0.5f, t.z, acc.z); acc.w = fmaf(0.5f, t.w, acc.w);
    t = noise_level<64>(V64, px, py, pz);
    acc.x = fmaf(0.25f, t.x, acc.x); acc.y = fmaf(0.25f, t.y, acc.y);
    acc.z = fmaf(0.25f, t.z, acc.z); acc.w = fmaf(0.25f, t.w, acc.w);
    t = noise_level<128>(V128, px, py, pz);
    acc.x = fmaf(0.125f, t.x, acc.x); acc.y = fmaf(0.125f, t.y, acc.y);
    acc.z = fmaf(0.125f, t.z, acc.z); acc.w = fmaf(0.125f, t.w, acc.w);
    out[i] = acc;
}

extern "C" void kernel_launch(void* const* d_in, const int* in_sizes, int n_in,
                              void* d_out, int out_size) {
    const float*  x    = (const float*)d_in[0];
    const float4* V16  = (const float4*)d_in[1];
    const float4* V32  = (const float4*)d_in[2];
    const float4* V64  = (const float4*)d_in[3];
    const float4* V128 = (const float4*)d_in[4];
    float4* out = (float4*)d_out;

    int n = in_sizes[0] / 3;

    if (n > MAX_POINTS) {
        int blocks = (n + 255) / 256;
        noise_direct_kernel<<<blocks, 256>>>(x, V16, V32, V64, V128, out, n);
        return;
    }

    int blocks = (n + 255) / 256;
    append_kernel<<<blocks, 256>>>(x, n);
    noise_group_kernel<<<NGC, GROUP_THREADS>>>(V16, V32, V64, V128, out);
}

// round 15
// speedup vs baseline: 1.2073x; 1.2073x over previous
#include <cuda_runtime.h>
#include <cuda_fp16.h>

// CompositeValueNoise v8 (R12 structure + trims):
//   Launch 1: persistent fused counting-sort (histo+scan+scatter, grid
//             barriers, ranks in registers). No zero phase — noise kernel
//             re-zeros g_hist for the next replay.
//   Launch 2: bucket-tiled noise kernel (1 CTA per coarse 16^3 cell; V16 f32,
//             V32/V64/V128 fp16 z-pair slots; f32x2 lerp tree).

#define MAX_POINTS 2000000
#define NB 32768
#define NG 4096
#define GROUP_THREADS 256

#define NCTA 592                 // 148 SMs x 4 resident CTAs
#define SORT_THREADS 256
#define TOTAL_T (NCTA * SORT_THREADS)
#define MAX_K 14                 // ceil(2e6 / 151552)
#define NCHUNK 512               // scan chunks
#define CHW 64                   // counters per chunk

__device__ int    g_hist[NB];    // static zero-init; noise kernel re-zeros
__device__ int    g_base[NB + 1];
__device__ float4 g_xs[MAX_POINTS];
__device__ int    g_chunksum[NCHUNK];
__device__ int    g_chunkbase[NCHUNK];
__device__ int    g_bar_count = 0;
__device__ volatile unsigned g_bar_gen = 0;

// ---------------------------------------------------------------------------
// grid barrier (all NCTA CTAs must be resident)
// ---------------------------------------------------------------------------
__device__ __forceinline__ void grid_barrier() {
    __syncthreads();
    if (threadIdx.x == 0) {
        unsigned gen = g_bar_gen;
        __threadfence();
        if (atomicAdd(&g_bar_count, 1) == NCTA - 1) {
            g_bar_count = 0;
            __threadfence();
            g_bar_gen = gen + 1;
        } else {
            while (g_bar_gen == gen) { __nanosleep(32); }
        }
        __threadfence();
    }
    __syncthreads();
}

__device__ __forceinline__ int bucket_key(float px, float py, float pz) {
    int kx = min((int)(px * 32.0f), 31);
    int ky = min((int)(py * 32.0f), 31);
    int kz = min((int)(pz * 32.0f), 31);
    int coarse = (((kx >> 1) * 16 + (ky >> 1)) * 16) + (kz >> 1);
    int fine = ((kx & 1) << 2) | ((ky & 1) << 1) | (kz & 1);
    return coarse * 8 + fine;
}

// ---------------------------------------------------------------------------
// persistent fused sort (g_hist arrives zeroed)
// ---------------------------------------------------------------------------
__global__ void __launch_bounds__(SORT_THREADS, 4)
sort_persistent_kernel(const float* __restrict__ x, int n) {
    int tid = threadIdx.x;
    int cta = blockIdx.x;
    int gtid = cta * SORT_THREADS + tid;

    // Phase 1: histogram + per-point rank & key in registers
    int ranks[MAX_K];
    int keys[MAX_K];
    #pragma unroll
    for (int k = 0; k < MAX_K; k++) {
        int i = gtid + k * TOTAL_T;
        if (i < n) {
            float px = __ldg(x + 3 * i);
            float py = __ldg(x + 3 * i + 1);
            float pz = __ldg(x + 3 * i + 2);
            keys[k] = bucket_key(px, py, pz);
            ranks[k] = atomicAdd(&g_hist[keys[k]], 1);
        }
    }
    grid_barrier();

    // Phase 2a: per-chunk local scan (CTAs 0..NCHUNK-1, lanes 0..CHW-1)
    int myval = 0, myincl = 0;
    if (cta < NCHUNK && tid < CHW) {
        int lane = tid & 31;
        int w = tid >> 5;            // 0 or 1
        myval = g_hist[cta * CHW + tid];
        int v = myval;
        #pragma unroll
        for (int off = 1; off < 32; off <<= 1) {
            int t = __shfl_up_sync(0xffffffffu, v, off);
            if (lane >= off) v += t;
        }
        myincl = v;
        __shared__ int w0tot;
        if (w == 0 && lane == 31) w0tot = v;
        __syncthreads();
        if (w == 1) myincl += w0tot;
        if (tid == CHW - 1) g_chunksum[cta] = myincl;
    } else {
        __syncthreads();             // match the scan CTAs' syncthreads
    }
    grid_barrier();

    // Phase 2b: CTA 0 scans chunk sums (512 values, 256 threads x 2)
    if (cta == 0) {
        __shared__ int wtot[8];
        int lane = tid & 31, w = tid >> 5;
        int a = g_chunksum[2 * tid];
        int b = g_chunksum[2 * tid + 1];
        int s = a + b;
        int v = s;
        #pragma unroll
        for (int off = 1; off < 32; off <<= 1) {
            int t = __shfl_up_sync(0xffffffffu, v, off);
            if (lane >= off) v += t;
        }
        if (lane == 31) wtot[w] = v;
        __syncthreads();
        int wbase = 0;
        #pragma unroll
        for (int ww = 0; ww < 8; ww++) wbase += (ww < w) ? wtot[ww] : 0;
        int excl = wbase + v - s;    // exclusive prefix of pair
        g_chunkbase[2 * tid] = excl;
        g_chunkbase[2 * tid + 1] = excl + a;
        if (tid == 255) g_base[NB] = wbase + v;   // total = n
    }
    grid_barrier();

    // Phase 2c: write g_base
    if (cta < NCHUNK && tid < CHW) {
        g_base[cta * CHW + tid] = g_chunkbase[cta] + myincl - myval;
    }
    grid_barrier();

    // Phase 3: scatter (atomic-free, keys+ranks from registers, x re-read L2-hot)
    #pragma unroll
    for (int k = 0; k < MAX_K; k++) {
        int i = gtid + k * TOTAL_T;
        if (i < n) {
            float px = __ldg(x + 3 * i);
            float py = __ldg(x + 3 * i + 1);
            float pz = __ldg(x + 3 * i + 2);
            int pos = __ldg(&g_base[keys[k]]) + ranks[k];
            g_xs[pos] = make_float4(px, py, pz, __int_as_float(i));
        }
    }
}

// ---------------------------------------------------------------------------
// packed f32x2 helpers
// ---------------------------------------------------------------------------
struct f2 { unsigned long long v; };

__device__ __forceinline__ f2 f2pk(float lo, float hi) {
    f2 r; asm("mov.b64 %0,{%1,%2};" : "=l"(r.v) : "f"(lo), "f"(hi)); return r;
}
__device__ __forceinline__ void f2up(f2 a, float& lo, float& hi) {
    asm("mov.b64 {%0,%1},%2;" : "=f"(lo), "=f"(hi) : "l"(a.v));
}
__device__ __forceinline__ f2 f2fma(f2 a, f2 b, f2 c) {
    f2 r; asm("fma.rn.f32x2 %0,%1,%2,%3;" : "=l"(r.v) : "l"(a.v), "l"(b.v), "l"(c.v));
    return r;
}
__device__ __forceinline__ f2 f2neg(f2 a) {
    f2 r; r.v = a.v ^ 0x8000000080000000ULL; return r;
}
__device__ __forceinline__ f2 f2lerp(f2 a, f2 b, f2 w, f2 nw) {
    return f2fma(w, b, f2fma(nw, a, a));
}
struct f2x2 { f2 a, b; };

__device__ __forceinline__ f2 h2f2(__half2 h) {
    float2 f = __half22float2(h);
    return f2pk(f.x, f.y);
}

__device__ __forceinline__ float smoothw(float t) {
    return (3.0f - 2.0f * t) * t * t;
}

// ---------------------------------------------------------------------------
// f32 level from smem float4 tile
// ---------------------------------------------------------------------------
template <int RES, int SX, int SY>
__device__ __forceinline__ f2x2 noise_f32(const float4* __restrict__ sm,
                                          int bx, int by, int bz,
                                          float px, float py, float pz) {
    const float r = (float)RES;
    float sx = px * r, sy = py * r, sz = pz * r;
    float fx = floorf(sx), fy = floorf(sy), fz = floorf(sz);
    float tx = sx - fx, ty = sy - fy, tz = sz - fz;
    int lx = (int)fx - bx, ly = (int)fy - by, lz = (int)fz - bz;

    f2 wz = f2pk(smoothw(tz), smoothw(tz)); f2 nwz = f2neg(wz);
    f2 wy = f2pk(smoothw(ty), smoothw(ty)); f2 nwy = f2neg(wy);
    f2 wx = f2pk(smoothw(tx), smoothw(tx)); f2 nwx = f2neg(wx);

    int idx = lx * SX + ly * SY + lz;
    float4 c000 = sm[idx],           c001 = sm[idx + 1];
    float4 c010 = sm[idx + SY],      c011 = sm[idx + SY + 1];
    float4 c100 = sm[idx + SX],      c101 = sm[idx + SX + 1];
    float4 c110 = sm[idx + SX + SY], c111 = sm[idx + SX + SY + 1];

    f2 z00a = f2lerp(f2pk(c000.x, c000.y), f2pk(c001.x, c001.y), wz, nwz);
    f2 z00b = f2lerp(f2pk(c000.z, c000.w), f2pk(c001.z, c001.w), wz, nwz);
    f2 z01a = f2lerp(f2pk(c010.x, c010.y), f2pk(c011.x, c011.y), wz, nwz);
    f2 z01b = f2lerp(f2pk(c010.z, c010.w), f2pk(c011.z, c011.w), wz, nwz);
    f2 z10a = f2lerp(f2pk(c100.x, c100.y), f2pk(c101.x, c101.y), wz, nwz);
    f2 z10b = f2lerp(f2pk(c100.z, c100.w), f2pk(c101.z, c101.w), wz, nwz);
    f2 z11a = f2lerp(f2pk(c110.x, c110.y), f2pk(c111.x, c111.y), wz, nwz);
    f2 z11b = f2lerp(f2pk(c110.z, c110.w), f2pk(c111.z, c111.w), wz, nwz);

    f2 y0a = f2lerp(z00a, z01a, wy, nwy);
    f2 y0b = f2lerp(z00b, z01b, wy, nwy);
    f2 y1a = f2lerp(z10a, z11a, wy, nwy);
    f2 y1b = f2lerp(z10b, z11b, wy, nwy);

    f2x2 o;
    o.a = f2lerp(y0a, y1a, wx, nwx);
    o.b = f2lerp(y0b, y1b, wx, nwx);
    return o;
}

// ---------------------------------------------------------------------------
// fp16 level from smem z-pair tile
// ---------------------------------------------------------------------------
template <int RES, int SX, int SY>
__device__ __forceinline__ f2x2 noise_f16(const uint4* __restrict__ smp,
                                          int bx, int by, int bz,
                                          float px, float py, float pz) {
    const float r = (float)RES;
    float sx = px * r, sy = py * r, sz = pz * r;
    float fx = floorf(sx), fy = floorf(sy), fz = floorf(sz);
    float tx = sx - fx, ty = sy - fy, tz = sz - fz;
    int lx = (int)fx - bx, ly = (int)fy - by, lz = (int)fz - bz;

    __half2 wz2 = __float2half2_rn(smoothw(tz));
    f2 wy = f2pk(smoothw(ty), smoothw(ty)); f2 nwy = f2neg(wy);
    f2 wx = f2pk(smoothw(tx), smoothw(tx)); f2 nwx = f2neg(wx);

    int idx = lx * SX + ly * SY + lz;
    uint4 q00 = smp[idx];
    uint4 q01 = smp[idx + SY];
    uint4 q10 = smp[idx + SX];
    uint4 q11 = smp[idx + SX + SY];

    #define ZL(q, out_a, out_b)                                                    \
        {                                                                          \
            __half2 a0 = *reinterpret_cast<const __half2*>(&(q).x);                \
            __half2 b0 = *reinterpret_cast<const __half2*>(&(q).y);                \
            __half2 a1 = *reinterpret_cast<const __half2*>(&(q).z);                \
            __half2 b1 = *reinterpret_cast<const __half2*>(&(q).w);                \
            out_a = __hfma2(wz2, __hsub2(a1, a0), a0);                             \
            out_b = __hfma2(wz2, __hsub2(b1, b0), b0);                             \
        }
    __half2 r00a, r00b, r01a, r01b, r10a, r10b, r11a, r11b;
    ZL(q00, r00a, r00b);
    ZL(q01, r01a, r01b);
    ZL(q10, r10a, r10b);
    ZL(q11, r11a, r11b);
    #undef ZL

    f2 y0a = f2lerp(h2f2(r00a), h2f2(r01a), wy, nwy);
    f2 y0b = f2lerp(h2f2(r00b), h2f2(r01b), wy, nwy);
    f2 y1a = f2lerp(h2f2(r10a), h2f2(r11a), wy, nwy);
    f2 y1b = f2lerp(h2f2(r10b), h2f2(r11b), wy, nwy);

    f2x2 o;
    o.a = f2lerp(y0a, y1a, wx, nwx);
    o.b = f2lerp(y0b, y1b, wx, nwx);
    return o;
}

// ---------------------------------------------------------------------------
// grouped noise kernel (staging issued before range gates; zeros g_hist)
// ---------------------------------------------------------------------------
__global__ void __launch_bounds__(GROUP_THREADS)
noise_group_kernel(const float4* __restrict__ V16,
                   const float4* __restrict__ V32,
                   const float4* __restrict__ V64,
                   const float4* __restrict__ V128,
                   float4* __restrict__ out) {
    int g = blockIdx.x;
    int tid = threadIdx.x;

    // re-zero this CTA's 8 histogram counters for the next graph replay
    if (tid < 8) g_hist[g * 8 + tid] = 0;

    int start = __ldg(&g_base[g * 8]);
    int end   = __ldg(&g_base[g * 8 + 8]);

    int cx = g >> 8, cy = (g >> 4) & 15, cz = g & 15;

    __shared__ uint4  smP128[648];
    __shared__ uint4  smP64[100];
    __shared__ uint4  smP32[18];
    __shared__ float4 smV16[8];

    #define PACK_PAIR(c0, c1, q)                                 \
        {                                                        \
            __half2 h0a = __floats2half2_rn((c0).x, (c0).y);     \
            __half2 h0b = __floats2half2_rn((c0).z, (c0).w);     \
            __half2 h1a = __floats2half2_rn((c1).x, (c1).y);     \
            __half2 h1b = __floats2half2_rn((c1).z, (c1).w);     \
            (q).x = *reinterpret_cast<unsigned*>(&h0a);          \
            (q).y = *reinterpret_cast<unsigned*>(&h0b);          \
            (q).z = *reinterpret_cast<unsigned*>(&h1a);          \
            (q).w = *reinterpret_cast<unsigned*>(&h1b);          \
        }

    for (int t = tid; t < 648; t += GROUP_THREADS) {
        int lx = t / 72, ly = (t / 8) % 9, lz = t % 8;
        long ofs = ((long)(8 * cx + lx) * 129 + (8 * cy + ly)) * 129 + (8 * cz + lz);
        float4 c0 = __ldg(V128 + ofs);
        float4 c1 = __ldg(V128 + ofs + 1);
        uint4 q; PACK_PAIR(c0, c1, q);
        smP128[t] = q;
    }
    for (int t = tid; t < 126; t += GROUP_THREADS) {
        if (t < 100) {
            int lx = t / 20, ly = (t / 4) % 5, lz = t % 4;
            long ofs = ((long)(4 * cx + lx) * 65 + (4 * cy + ly)) * 65 + (4 * cz + lz);
            float4 c0 = __ldg(V64 + ofs);
            float4 c1 = __ldg(V64 + ofs + 1);
            uint4 q; PACK_PAIR(c0, c1, q);
            smP64[t] = q;
        } else if (t < 118) {
            int u = t - 100;
            int lx = u / 6, ly = (u / 2) % 3, lz = u % 2;
            long ofs = ((long)(2 * cx + lx) * 33 + (2 * cy + ly)) * 33 + (2 * cz + lz);
            float4 c0 = __ldg(V32 + ofs);
            float4 c1 = __ldg(V32 + ofs + 1);
            uint4 q; PACK_PAIR(c0, c1, q);
            smP32[u] = q;
        } else {
            int u = t - 118;
            int lx = (u >> 2) & 1, ly = (u >> 1) & 1, lz = u & 1;
            smV16[lx * 4 + ly * 2 + lz] =
                __ldg(V16 + ((cx + lx) * 17 + (cy + ly)) * 17 + (cz + lz));
        }
    }
    #undef PACK_PAIR
    __syncthreads();

    for (int j = start + tid; j < end; j += GROUP_THREADS) {
        float4 p = g_xs[j];
        float px = p.x, py = p.y, pz = p.z;
        int orig = __float_as_int(p.w);

        f2x2 acc = noise_f32<16, 4, 2>(smV16, cx, cy, cz, px, py, pz);

        f2x2 t32 = noise_f16<32, 6, 2>(smP32, 2 * cx, 2 * cy, 2 * cz, px, py, pz);
        f2 m05 = f2pk(0.5f, 0.5f);
        acc.a = f2fma(m05, t32.a, acc.a);
        acc.b = f2fma(m05, t32.b, acc.b);

        f2x2 t64 = noise_f16<64, 20, 4>(smP64, 4 * cx, 4 * cy, 4 * cz, px, py, pz);
        f2 m025 = f2pk(0.25f, 0.25f);
        acc.a = f2fma(m025, t64.a, acc.a);
        acc.b = f2fma(m025, t64.b, acc.b);

        f2x2 t128 = noise_f16<128, 72, 8>(smP128, 8 * cx, 8 * cy, 8 * cz, px, py, pz);
        f2 m0125 = f2pk(0.125f, 0.125f);
        acc.a = f2fma(m0125, t128.a, acc.a);
        acc.b = f2fma(m0125, t128.b, acc.b);

        float4 o;
        f2up(acc.a, o.x, o.y);
        f2up(acc.b, o.z, o.w);
        out[orig] = o;
    }
}

// ---------------------------------------------------------------------------
// fallback (unsorted, full f32) if n exceeds static scratch
// ---------------------------------------------------------------------------
__device__ __forceinline__ float4 lerp4g(const float4 a, const float4 b, const float t) {
    return make_float4(fmaf(t, b.x - a.x, a.x),
                       fmaf(t, b.y - a.y, a.y),
                       fmaf(t, b.z - a.z, a.z),
                       fmaf(t, b.w - a.w, a.w));
}
template <int RES>
__device__ __forceinline__ float4 noise_level(const float4* __restrict__ V,
                                              float px, float py, float pz) {
    const float r = (float)RES;
    float sx = px * r, sy = py * r, sz = pz * r;
    float fx = floorf(sx), fy = floorf(sy), fz = floorf(sz);
    float tx = sx - fx, ty = sy - fy, tz = sz - fz;
    int ix = min((int)fx, RES - 1);
    int iy = min((int)fy, RES - 1);
    int iz = min((int)fz, RES - 1);
    float wx = smoothw(tx), wy = smoothw(ty), wz = smoothw(tz);
    const int S = RES + 1, SY = S, SX = S * S;
    int base = (ix * S + iy) * S + iz;
    float4 c000 = __ldg(V + base);
    float4 c001 = __ldg(V + base + 1);
    float4 c010 = __ldg(V + base + SY);
    float4 c011 = __ldg(V + base + SY + 1);
    float4 c100 = __ldg(V + base + SX);
    float4 c101 = __ldg(V + base + SX + 1);
    float4 c110 = __ldg(V + base + SX + SY);
    float4 c111 = __ldg(V + base + SX + SY + 1);
    float4 az = lerp4g(c000, c001, wz);
    float4 bz = lerp4g(c010, c011, wz);
    float4 cz = lerp4g(c100, c101, wz);
    float4 dz = lerp4g(c110, c111, wz);
    float4 ay = lerp4g(az, bz, wy);
    float4 by = lerp4g(cz, dz, wy);
    return lerp4g(ay, by, wx);
}

__global__ void __launch_bounds__(256)
noise_direct_kernel(const float* __restrict__ x,
                    const float4* __restrict__ V16,
                    const float4* __restrict__ V32,
                    const float4* __restrict__ V64,
                    const float4* __restrict__ V128,
                    float4* __restrict__ out,
                    int n) {
    int i = blockIdx.x * blockDim.x + threadIdx.x;
    if (i >= n) return;
    float px = x[3 * i], py = x[3 * i + 1], pz = x[3 * i + 2];
    float4 acc = noise_level<16>(V16, px, py, pz);
    float4 t;
    t = noise_level<32>(V32, px, py, pz);
    acc.x = fmaf(0.5f, t.x, acc.x); acc.y = fmaf(0.5f, t.y, acc.y);
    acc.z = fmaf(0.5f, t.z, acc.z); acc.w = fmaf(0.5f, t.w, acc.w);
    t = noise_level<64>(V64, px, py, pz);
    acc.x = fmaf(0.25f, t.x, acc.x); acc.y = fmaf(0.25f, t.y, acc.y);
    acc.z = fmaf(0.25f, t.z, acc.z); acc.w = fmaf(0.25f, t.w, acc.w);
    t = noise_level<128>(V128, px, py, pz);
    acc.x = fmaf(0.125f, t.x, acc.x); acc.y = fmaf(0.125f, t.y, acc.y);
    acc.z = fmaf(0.125f, t.z, acc.z); acc.w = fmaf(0.125f, t.w, acc.w);
    out[i] = acc;
}

extern "C" void kernel_launch(void* const* d_in, const int* in_sizes, int n_in,
                              void* d_out, int out_size) {
    const float*  x    = (const float*)d_in[0];
    const float4* V16  = (const float4*)d_in[1];
    const float4* V32  = (const float4*)d_in[2];
    const float4* V64  = (const float4*)d_in[3];
    const float4* V128 = (const float4*)d_in[4];
    float4* out = (float4*)d_out;

    int n = in_sizes[0] / 3;

    if (n > MAX_POINTS) {
        int blocks = (n + 255) / 256;
        noise_direct_kernel<<<blocks, 256>>>(x, V16, V32, V64, V128, out, n);
        return;
    }

    sort_persistent_kernel<<<NCTA, SORT_THREADS>>>(x, n);
    noise_group_kernel<<<NG, GROUP_THREADS>>>(V16, V32, V64, V128, out);
}